// round 6
// baseline (speedup 1.0000x reference)
#include <cuda_runtime.h>
#include <cstdint>

// Problem constants: T tables, E rows/table, D dim, B batch, L bag length
constexpr int T = 4;
constexpr int E = 1000000;
constexpr int D = 128;
constexpr int B = 8192;
constexpr int L = 32;

// One warp per (t, b) bag. Lane l owns float4 chunk l of the D=128 row.
// indices: int32 [T, B, L] (JAX default x64-disabled => int32!)
// weights: fp32 [T, E, D]; out: fp32 [B, T*D]
__global__ void __launch_bounds__(256) embbag_kernel(
    const int* __restrict__ indices,
    const float* __restrict__ weights,
    float* __restrict__ out)
{
    const int warp_global = (blockIdx.x * blockDim.x + threadIdx.x) >> 5;
    const int lane = threadIdx.x & 31;
    if (warp_global >= T * B) return;

    const int t = warp_global / B;
    const int b = warp_global % B;

    // Coalesced per-warp index load: lane l reads index l of this bag (128B).
    const int my_idx = indices[((size_t)t * B + b) * L + lane];

    // Base of this table, as float4 rows of 32 chunks.
    const float4* __restrict__ wbase =
        reinterpret_cast<const float4*>(weights) + (size_t)t * E * (D / 4);

    float4 acc = make_float4(0.f, 0.f, 0.f, 0.f);

#pragma unroll
    for (int j = 0; j < L; j++) {
        const int r = __shfl_sync(0xFFFFFFFFu, my_idx, j);
        const float4 v = __ldg(wbase + (size_t)r * (D / 4) + lane);
        acc.x += v.x;
        acc.y += v.y;
        acc.z += v.z;
        acc.w += v.w;
    }

    // out[b][t*D + lane*4 ..] as float4
    float4* __restrict__ o =
        reinterpret_cast<float4*>(out) + ((size_t)b * T + t) * (D / 4) + lane;
    *o = acc;
}

extern "C" void kernel_launch(void* const* d_in, const int* in_sizes, int n_in,
                              void* d_out, int out_size)
{
    const int*   indices = (const int*)d_in[0];   // [T, B, L] int32
    const float* weights = (const float*)d_in[1]; // [T, E, D] fp32
    float*       out     = (float*)d_out;         // [B, T*D] fp32

    const int total_warps = T * B;            // 32768
    const int threads = 256;                  // 8 warps/block
    const int blocks = (total_warps * 32 + threads - 1) / threads; // 4096

    embbag_kernel<<<blocks, threads>>>(indices, weights, out);
}